// round 8
// baseline (speedup 1.0000x reference)
#include <cuda_runtime.h>
#include <cuda_fp16.h>
#include <cuda_bf16.h>

#define D_IN   128
#define D_OUT  64
#define MAX_NODES 65536
#define MAX_EDGES 1048576
#define MAX_CHUNKS 64        // scan chunks of 1024; N=50000 -> 49

// Scratch (device globals; zero-initialized at module load).
// Invariants restored by aggregate_kernel each call: g_cnt == 0, g_status == 0.
__device__ __half             g_h[(size_t)MAX_NODES * D_OUT];
__device__ int                g_cnt[MAX_NODES];
__device__ int                g_row_ptr[MAX_NODES];
__device__ int                g_fill_ptr[MAX_NODES];
__device__ int                g_adj[MAX_EDGES];
__device__ unsigned long long g_status[MAX_CHUNKS];   // lookback: (sum<<2)|flag

// ---------------------------------------------------------------------------
// f32x2 packed helpers
// ---------------------------------------------------------------------------
__device__ __forceinline__ unsigned long long pk2(float a, float b) {
    unsigned long long r;
    asm("mov.b64 %0, {%1, %2};" : "=l"(r) : "f"(a), "f"(b));
    return r;
}
__device__ __forceinline__ void ffma2(unsigned long long& d,
                                      unsigned long long a,
                                      unsigned long long b) {
    asm("fma.rn.f32x2 %0, %1, %2, %3;" : "=l"(d) : "l"(a), "l"(b), "l"(d));
}
__device__ __forceinline__ float2 upk2(unsigned long long v) {
    float2 f;
    asm("mov.b64 {%0, %1}, %2;" : "=f"(f.x), "=f"(f.y) : "l"(v));
    return f;
}

// ---------------------------------------------------------------------------
// K1 (side stream): in-degree histogram. Relies on g_cnt == 0 at entry.
// ---------------------------------------------------------------------------
__global__ void hist_kernel(const int* __restrict__ row, int E) {
    int e = blockIdx.x * blockDim.x + threadIdx.x;
    if (e < E) atomicAdd(&g_cnt[__ldg(&row[e])], 1);
}

// ---------------------------------------------------------------------------
// K2 (side stream): single-pass exclusive scan with decoupled lookback.
// One block per 1024 counts (256 thr x int4). All blocks fit in one wave.
// flag: 0=not ready, 1=aggregate, 2=inclusive prefix.
// ---------------------------------------------------------------------------
__global__ void __launch_bounds__(256) scan_kernel() {
    __shared__ int wsum[8];
    __shared__ int s_base;
    const int bid = blockIdx.x, tid = threadIdx.x, lane = tid & 31, w = tid >> 5;

    int base = bid * 1024 + tid * 4;
    int4 v = *(const int4*)&g_cnt[base];
    int tsum = v.x + v.y + v.z + v.w;

    int inc = tsum;
#pragma unroll
    for (int off = 1; off < 32; off <<= 1) {
        int t = __shfl_up_sync(~0u, inc, off);
        if (lane >= off) inc += t;
    }
    if (lane == 31) wsum[w] = inc;
    __syncthreads();
    if (w == 0 && lane < 8) {
        int x = wsum[lane];
#pragma unroll
        for (int off = 1; off < 8; off <<= 1) {
            int t = __shfl_up_sync(0xff, x, off);
            if (lane >= off) x += t;
        }
        wsum[lane] = x;
    }
    __syncthreads();

    int block_total = wsum[7];

    if (tid == 0) {
        if (bid == 0) {
            atomicExch(&g_status[0], ((unsigned long long)block_total << 2) | 2ull);
            s_base = 0;
        } else {
            atomicExch(&g_status[bid], ((unsigned long long)block_total << 2) | 1ull);
            int sum = 0;
            for (int p = bid - 1; p >= 0; p--) {
                unsigned long long st;
                do { st = atomicAdd(&g_status[p], 0ull); } while ((st & 3ull) == 0ull);
                sum += (int)(st >> 2);
                if ((st & 3ull) == 2ull) break;
            }
            atomicExch(&g_status[bid],
                       ((unsigned long long)(sum + block_total) << 2) | 2ull);
            s_base = sum;
        }
    }
    __syncthreads();

    int prefix = s_base + (w > 0 ? wsum[w - 1] : 0) + (inc - tsum);
    int e0 = prefix;
    int e1 = e0 + v.x, e2 = e1 + v.y, e3 = e2 + v.z;
    int4 ev = make_int4(e0, e1, e2, e3);
    *(int4*)&g_row_ptr[base]  = ev;
    *(int4*)&g_fill_ptr[base] = ev;
}

// ---------------------------------------------------------------------------
// K3 (side stream): fill adjacency
// ---------------------------------------------------------------------------
__global__ void fill_kernel(const int* __restrict__ row,
                            const int* __restrict__ col, int E) {
    int e = blockIdx.x * blockDim.x + threadIdx.x;
    if (e >= E) return;
    int r = __ldg(&row[e]);
    int pos = atomicAdd(&g_fill_ptr[r], 1);
    g_adj[pos] = __ldg(&col[e]);
}

// ---------------------------------------------------------------------------
// K4 (main stream): GEMM h = x @ W^T + b (f32x2 FMA), stores fp16.
// ---------------------------------------------------------------------------
__global__ void __launch_bounds__(128) gemm_kernel(
    const float* __restrict__ x, const float* __restrict__ W,
    const float* __restrict__ b, int N)
{
    __shared__ float4 xs[64][33];
    __shared__ float4 ws[64][33];

    const int tid = threadIdx.x;
    const int nb  = blockIdx.x * 64;

    const float4* W4 = (const float4*)W;
#pragma unroll
    for (int i = 0; i < 16; i++) {
        int lin = tid + 128 * i;
        int r = lin >> 5, c = lin & 31;
        ws[r][c] = W4[lin];
    }
    const float4* x4 = (const float4*)x;
#pragma unroll
    for (int i = 0; i < 16; i++) {
        int lin = tid + 128 * i;
        int r = lin >> 5, c = lin & 31;
        int node = nb + r;
        float4 v = make_float4(0.f, 0.f, 0.f, 0.f);
        if (node < N) v = x4[node * 32 + c];
        xs[r][c] = v;
    }
    __syncthreads();

    const int tx = tid & 15;
    const int ty = tid >> 4;

    unsigned long long acc[8][4];
#pragma unroll
    for (int i = 0; i < 8; i++)
#pragma unroll
        for (int j = 0; j < 4; j++) acc[i][j] = 0ull;

#pragma unroll 4
    for (int k = 0; k < 32; k++) {
        unsigned long long xlo[8], xhi[8], wlo[4], whi[4];
#pragma unroll
        for (int i = 0; i < 8; i++) {
            float4 v = xs[ty + 8 * i][k];
            xlo[i] = pk2(v.x, v.y);
            xhi[i] = pk2(v.z, v.w);
        }
#pragma unroll
        for (int j = 0; j < 4; j++) {
            float4 v = ws[tx + 16 * j][k];
            wlo[j] = pk2(v.x, v.y);
            whi[j] = pk2(v.z, v.w);
        }
#pragma unroll
        for (int i = 0; i < 8; i++) {
#pragma unroll
            for (int j = 0; j < 4; j++) {
                ffma2(acc[i][j], xlo[i], wlo[j]);
                ffma2(acc[i][j], xhi[i], whi[j]);
            }
        }
    }

    float bias[4];
#pragma unroll
    for (int j = 0; j < 4; j++) bias[j] = __ldg(&b[tx + 16 * j]);

#pragma unroll
    for (int i = 0; i < 8; i++) {
        int node = nb + ty + 8 * i;
        if (node < N) {
#pragma unroll
            for (int j = 0; j < 4; j++) {
                float2 p = upk2(acc[i][j]);
                g_h[(size_t)node * D_OUT + tx + 16 * j] =
                    __float2half(p.x + p.y + bias[j]);
            }
        }
    }
}

// ---------------------------------------------------------------------------
// K5 (main, after join): aggregate + normalize + write + restore invariants.
// One warp per node; lane owns one __half2. 8-deep scalar-adj MLP.
// ---------------------------------------------------------------------------
__global__ void __launch_bounds__(256) aggregate_kernel(float* __restrict__ out, int N)
{
    // restore lookback-status invariant for next replay
    if (blockIdx.x == 0 && threadIdx.x < MAX_CHUNKS)
        g_status[threadIdx.x] = 0ull;

    int node = (blockIdx.x * blockDim.x + threadIdx.x) >> 5;
    int lane = threadIdx.x & 31;
    if (node >= N) return;

    int start = __ldg(&g_row_ptr[node]);
    int deg   = __ldg(&g_cnt[node]);
    if (lane == 0) g_cnt[node] = 0;   // restore cnt invariant

    const __half2* h2 = (const __half2*)g_h;
    float2 acc = make_float2(0.f, 0.f);

    int j = 0;
    for (; j + 8 <= deg; j += 8) {
        int c0 = __ldg(&g_adj[start + j]);
        int c1 = __ldg(&g_adj[start + j + 1]);
        int c2 = __ldg(&g_adj[start + j + 2]);
        int c3 = __ldg(&g_adj[start + j + 3]);
        int c4 = __ldg(&g_adj[start + j + 4]);
        int c5 = __ldg(&g_adj[start + j + 5]);
        int c6 = __ldg(&g_adj[start + j + 6]);
        int c7 = __ldg(&g_adj[start + j + 7]);
        float2 f0 = __half22float2(h2[c0 * 32 + lane]);
        float2 f1 = __half22float2(h2[c1 * 32 + lane]);
        float2 f2 = __half22float2(h2[c2 * 32 + lane]);
        float2 f3 = __half22float2(h2[c3 * 32 + lane]);
        float2 f4 = __half22float2(h2[c4 * 32 + lane]);
        float2 f5 = __half22float2(h2[c5 * 32 + lane]);
        float2 f6 = __half22float2(h2[c6 * 32 + lane]);
        float2 f7 = __half22float2(h2[c7 * 32 + lane]);
        acc.x += ((f0.x + f1.x) + (f2.x + f3.x)) + ((f4.x + f5.x) + (f6.x + f7.x));
        acc.y += ((f0.y + f1.y) + (f2.y + f3.y)) + ((f4.y + f5.y) + (f6.y + f7.y));
    }
    for (; j < deg; j++) {
        int c = __ldg(&g_adj[start + j]);
        float2 f = __half22float2(h2[c * 32 + lane]);
        acc.x += f.x; acc.y += f.y;
    }

    float d = fmaxf((float)deg, 1.0f);
    acc.x /= d; acc.y /= d;
    ((float2*)out)[node * 32 + lane] = acc;
}

// ---------------------------------------------------------------------------
extern "C" void kernel_launch(void* const* d_in, const int* in_sizes, int n_in,
                              void* d_out, int out_size)
{
    const float* x   = (const float*)d_in[0];
    const float* W   = (const float*)d_in[1];
    const float* b   = (const float*)d_in[2];
    const int*   row = (const int*)d_in[3];
    const int*   col = (const int*)d_in[4];
    float* out = (float*)d_out;

    int N = in_sizes[0] / D_IN;   // 50000
    int E = in_sizes[3];          // 800000

    int nchunks = (N + 1023) / 1024;   // 49

    // One-time host-side setup (first call is the non-captured correctness run;
    // no device memory is allocated here).
    static cudaStream_t s_side = nullptr;
    static cudaEvent_t  ev_fork = nullptr, ev_join = nullptr;
    if (s_side == nullptr) {
        cudaStreamCreateWithFlags(&s_side, cudaStreamNonBlocking);
        cudaEventCreateWithFlags(&ev_fork, cudaEventDisableTiming);
        cudaEventCreateWithFlags(&ev_join, cudaEventDisableTiming);
    }

    // Fork: CSR build chain on side stream, GEMM on main stream.
    cudaEventRecord(ev_fork, 0);
    cudaStreamWaitEvent(s_side, ev_fork, 0);

    hist_kernel<<<(E + 255) / 256, 256, 0, s_side>>>(row, E);
    scan_kernel<<<nchunks, 256, 0, s_side>>>();
    fill_kernel<<<(E + 255) / 256, 256, 0, s_side>>>(row, col, E);
    cudaEventRecord(ev_join, s_side);

    gemm_kernel<<<(N + 63) / 64, 128>>>(x, W, b, N);

    // Join, then aggregate.
    cudaStreamWaitEvent(0, ev_join, 0);
    long long total = (long long)N * 32;
    aggregate_kernel<<<(int)((total + 255) / 256), 256>>>(out, N);
}